// round 11
// baseline (speedup 1.0000x reference)
#include <cuda_runtime.h>
#include <cuda_fp16.h>
#include <math.h>

#define BATCH 16
#define SEQ   1024
#define DM    512
#define NH    8
#define HD    64
#define NB    (NH*BATCH)

#define A_LD  40    // proj A tile pitch (halves)
#define B_LD  136   // proj B tile pitch (halves), 128+8
#define T_LD  72    // attn Q/K/V/P tile pitch (halves)

// Scratch, fp16 (device globals: allocation-free per harness rules).
__device__ __half g_Q[(size_t)NB*SEQ*HD];   // pre-scaled by 0.125
__device__ __half g_K[(size_t)NB*SEQ*HD];
__device__ __half g_V[(size_t)NB*SEQ*HD];
__device__ __half g_A[(size_t)NB*SEQ*HD];
__device__ __half g_xh[(size_t)BATCH*SEQ*DM];   // fp16 copy of x
__device__ __half g_wh[4][(size_t)DM*DM];       // fp16 wq,wk,wv,wo

__device__ __forceinline__ void st_h4(__half* p, float4 v) {
    __half2 lo = __floats2half2_rn(v.x, v.y);
    __half2 hi = __floats2half2_rn(v.z, v.w);
    uint2 u;
    u.x = *(unsigned int*)&lo;
    u.y = *(unsigned int*)&hi;
    *(uint2*)p = u;
}

// ---------------------------------------------------------------------------
// PTX mma/ldmatrix helpers
// ---------------------------------------------------------------------------
__device__ __forceinline__ unsigned su(const void* p) {
    return (unsigned)__cvta_generic_to_shared(p);
}
__device__ __forceinline__ void ldsm4(unsigned& r0, unsigned& r1,
                                      unsigned& r2, unsigned& r3, unsigned a) {
    asm volatile("ldmatrix.sync.aligned.m8n8.x4.shared.b16 {%0,%1,%2,%3},[%4];"
                 : "=r"(r0), "=r"(r1), "=r"(r2), "=r"(r3) : "r"(a));
}
__device__ __forceinline__ void ldsm4t(unsigned& r0, unsigned& r1,
                                       unsigned& r2, unsigned& r3, unsigned a) {
    asm volatile("ldmatrix.sync.aligned.m8n8.x4.trans.shared.b16 {%0,%1,%2,%3},[%4];"
                 : "=r"(r0), "=r"(r1), "=r"(r2), "=r"(r3) : "r"(a));
}
__device__ __forceinline__ void mma_f16(float* d, const unsigned* a,
                                        const unsigned* b) {
    asm volatile("mma.sync.aligned.m16n8k16.row.col.f32.f16.f16.f32 "
                 "{%0,%1,%2,%3},{%4,%5,%6,%7},{%8,%9},{%0,%1,%2,%3};"
                 : "+f"(d[0]), "+f"(d[1]), "+f"(d[2]), "+f"(d[3])
                 : "r"(a[0]), "r"(a[1]), "r"(a[2]), "r"(a[3]),
                   "r"(b[0]), "r"(b[1]));
}

// ---------------------------------------------------------------------------
// fp32 -> fp16 conversion prep kernels
// ---------------------------------------------------------------------------
__global__ __launch_bounds__(256) void cvt_kernel(const float* __restrict__ src,
                                                  __half* __restrict__ dst, int n) {
    int i = (blockIdx.x * 256 + threadIdx.x) * 4;
    if (i < n) st_h4(dst + i, *(const float4*)(src + i));
}
__global__ __launch_bounds__(256) void cvt_w_kernel(
    const float* __restrict__ wq, const float* __restrict__ wk,
    const float* __restrict__ wv, const float* __restrict__ wo) {
    const float* src = (blockIdx.y == 0) ? wq : (blockIdx.y == 1) ? wk
                     : (blockIdx.y == 2) ? wv : wo;
    __half* dst = g_wh[blockIdx.y];
    int i = (blockIdx.x * 256 + threadIdx.x) * 4;
    st_h4(dst + i, *(const float4*)(src + i));
}

// ---------------------------------------------------------------------------
// QKV projection, PTX mma, register epilogue, double-buffered smem (1 sync/iter).
// Block 128x128, BK=32, 8 warps (4M x 2N), warp tile 32x64.
// ---------------------------------------------------------------------------
__global__ __launch_bounds__(256, 2) void proj_qkv_kernel(
    const float* __restrict__ bq, const float* __restrict__ bk,
    const float* __restrict__ bv)
{
    __shared__ __half As[2][128*A_LD];
    __shared__ __half Bs[2][32*B_LD];

    const float* bias; __half* dst; float oscale;
    const __half* w = g_wh[blockIdx.z];
    if (blockIdx.z == 0)      { bias = bq; dst = g_Q; oscale = 0.125f; }
    else if (blockIdx.z == 1) { bias = bk; dst = g_K; oscale = 1.f; }
    else                      { bias = bv; dst = g_V; oscale = 1.f; }

    const int m0 = blockIdx.x * 128;
    const int n0 = blockIdx.y * 128;
    const int tid = threadIdx.x;
    const int wid = tid >> 5, lane = tid & 31;
    const int wm = wid >> 1, wn = wid & 1;
    const int quad = lane >> 2, lane4 = lane & 3;
    const int sub = lane >> 3, lr8 = lane & 7;
    const int a_r = (sub & 1)*8 + lr8, a_c = (sub >> 1)*8;

    const int ar = tid >> 3, ac = (tid & 7) * 4;
    const int br = tid >> 5, bc = (tid & 31) * 4;

    float o[2][8][4];
    #pragma unroll
    for (int i = 0; i < 2; i++)
        #pragma unroll
        for (int j = 0; j < 8; j++)
            #pragma unroll
            for (int e = 0; e < 4; e++) o[i][j][e] = 0.f;

    float2 bias2[8];
    #pragma unroll
    for (int nf = 0; nf < 8; nf++)
        bias2[nf] = *(const float2*)(bias + n0 + wn*64 + nf*8 + lane4*2);

    uint2 ra[4], rb[4];
    #pragma unroll
    for (int it = 0; it < 4; it++)
        ra[it] = *(const uint2*)(g_xh + (size_t)(m0 + ar + it*32)*DM + ac);
    #pragma unroll
    for (int it = 0; it < 4; it++)
        rb[it] = *(const uint2*)(w + (size_t)(br + it*8)*DM + n0 + bc);

    const unsigned ab[2] = {su(As[0]), su(As[1])};
    const unsigned bb[2] = {su(Bs[0]), su(Bs[1])};

    for (int kt = 0; kt < 16; kt++) {
        const int cb = kt & 1;
        #pragma unroll
        for (int it = 0; it < 4; it++)
            *(uint2*)(As[cb] + (ar + it*32)*A_LD + ac) = ra[it];
        #pragma unroll
        for (int it = 0; it < 4; it++)
            *(uint2*)(Bs[cb] + (br + it*8)*B_LD + bc) = rb[it];
        __syncthreads();

        if (kt < 15) {
            int k0 = (kt + 1) * 32;
            #pragma unroll
            for (int it = 0; it < 4; it++)
                ra[it] = *(const uint2*)(g_xh + (size_t)(m0 + ar + it*32)*DM + k0 + ac);
            #pragma unroll
            for (int it = 0; it < 4; it++)
                rb[it] = *(const uint2*)(w + (size_t)(k0 + br + it*8)*DM + n0 + bc);
        }

        #pragma unroll
        for (int kf = 0; kf < 2; kf++) {
            unsigned a[2][4], b[8][2];
            #pragma unroll
            for (int mf = 0; mf < 2; mf++)
                ldsm4(a[mf][0], a[mf][1], a[mf][2], a[mf][3],
                      ab[cb] + ((wm*32 + mf*16 + a_r)*A_LD + kf*16 + a_c)*2);
            #pragma unroll
            for (int nb = 0; nb < 4; nb++) {
                unsigned r0, r1, r2, r3;
                ldsm4t(r0, r1, r2, r3,
                       bb[cb] + ((kf*16 + (sub & 1)*8 + lr8)*B_LD
                                 + wn*64 + nb*16 + (sub >> 1)*8)*2);
                b[nb*2+0][0] = r0; b[nb*2+0][1] = r1;
                b[nb*2+1][0] = r2; b[nb*2+1][1] = r3;
            }
            #pragma unroll
            for (int mf = 0; mf < 2; mf++)
                #pragma unroll
                for (int nf = 0; nf < 8; nf++)
                    mma_f16(o[mf][nf], a[mf], b[nf]);
        }
    }

    // Register-direct epilogue: bias, scale, fp16 scatter (head-major).
    #pragma unroll
    for (int mf = 0; mf < 2; mf++) {
        int row0 = m0 + wm*32 + mf*16 + quad;
        int b0 = row0 >> 10, s0 = row0 & 1023;
        int row1 = row0 + 8;
        int b1 = row1 >> 10, s1 = row1 & 1023;
        #pragma unroll
        for (int nf = 0; nf < 8; nf++) {
            int col = n0 + wn*64 + nf*8 + lane4*2;
            int h = col >> 6, q0 = col & 63;
            *(__half2*)(dst + (((size_t)(h*BATCH + b0))*SEQ + s0)*HD + q0) =
                __floats2half2_rn((o[mf][nf][0] + bias2[nf].x) * oscale,
                                  (o[mf][nf][1] + bias2[nf].y) * oscale);
            *(__half2*)(dst + (((size_t)(h*BATCH + b1))*SEQ + s1)*HD + q0) =
                __floats2half2_rn((o[mf][nf][2] + bias2[nf].x) * oscale,
                                  (o[mf][nf][3] + bias2[nf].y) * oscale);
        }
    }
}

// ---------------------------------------------------------------------------
// Fused attention (unchanged from R10): PTX mma + register softmax.
// ---------------------------------------------------------------------------
#define QT_ROWS 128
#define ATTN_SMEM (2*128*T_LD*2 + 2*64*T_LD*2 + 1024*4 + 2*128*4)

__global__ __launch_bounds__(256, 2) void attn_kernel(const int* __restrict__ pmask,
                                                      float* __restrict__ raw)
{
    extern __shared__ char shb[];
    __half* Qs = (__half*)shb;
    __half* Ps = Qs + 128*T_LD;
    __half* Ks = Ps + 128*T_LD;
    __half* Vs = Ks + 64*T_LD;
    float*  mm = (float*)(Vs + 64*T_LD);
    float*  ls = mm + 1024;

    const int n  = blockIdx.y;
    const int qt = blockIdx.x;
    const int tid = threadIdx.x;
    const int wid = tid >> 5, lane = tid & 31;
    const int wm = wid >> 1, wn = wid & 1;
    const int quad = lane >> 2, lane4 = lane & 3;
    const int sub = lane >> 3, lr8 = lane & 7;
    const int mb = n >> 3;

    const int a_r = (sub & 1)*8 + lr8, a_c = (sub >> 1)*8;
    const int b_r = (sub >> 1)*8 + lr8, b_c = (sub & 1)*8;

    const __half* qsrc = g_Q + ((size_t)n*SEQ + qt*128)*HD;
    #pragma unroll
    for (int it = 0; it < 8; it++) {
        int idx = tid + it*256;
        int r = idx >> 4, d0 = (idx & 15) * 4;
        *(uint2*)(Qs + r*T_LD + d0) = *(const uint2*)(qsrc + r*HD + d0);
    }
    {
        int4 m4 = *(const int4*)(pmask + (size_t)mb*SEQ + tid*4);
        float4 f4;
        f4.x = m4.x ? 1.f : 0.f; f4.y = m4.y ? 1.f : 0.f;
        f4.z = m4.z ? 1.f : 0.f; f4.w = m4.w ? 1.f : 0.f;
        *(float4*)(mm + tid*4) = f4;
    }

    const __half* ksrc = g_K + (size_t)n*SEQ*HD;
    const __half* vsrc = g_V + (size_t)n*SEQ*HD;
    const int lr = tid >> 4, ld0 = (tid & 15) * 4;

    float o[2][4][4];
    #pragma unroll
    for (int i = 0; i < 2; i++)
        #pragma unroll
        for (int j = 0; j < 4; j++)
            #pragma unroll
            for (int e = 0; e < 4; e++) o[i][j][e] = 0.f;
    float rs[2][2] = {{0.f, 0.f}, {0.f, 0.f}};

    uint2 rk[4], rv[4];
    #pragma unroll
    for (int it = 0; it < 4; it++) {
        int t = lr + it*16;
        rk[it] = *(const uint2*)(ksrc + (size_t)t*HD + ld0);
        rv[it] = *(const uint2*)(vsrc + (size_t)t*HD + ld0);
    }

    const unsigned qb = su(Qs), pb = su(Ps), kb = su(Ks), vb = su(Vs);
    const size_t rowg = (size_t)n*SEQ + (size_t)qt*128;

    for (int kt = 0; kt < 16; ++kt) {
        __syncthreads();
        #pragma unroll
        for (int it = 0; it < 4; it++) {
            int t = lr + it*16;
            *(uint2*)(Ks + t*T_LD + ld0) = rk[it];
            *(uint2*)(Vs + t*T_LD + ld0) = rv[it];
        }
        __syncthreads();

        float s[2][4][4];
        #pragma unroll
        for (int i = 0; i < 2; i++)
            #pragma unroll
            for (int j = 0; j < 4; j++)
                #pragma unroll
                for (int e = 0; e < 4; e++) s[i][j][e] = 0.f;

        #pragma unroll
        for (int kf = 0; kf < 4; kf++) {
            unsigned a[2][4], b[4][2];
            #pragma unroll
            for (int mf = 0; mf < 2; mf++)
                ldsm4(a[mf][0], a[mf][1], a[mf][2], a[mf][3],
                      qb + ((wm*32 + mf*16 + a_r)*T_LD + kf*16 + a_c)*2);
            #pragma unroll
            for (int nb = 0; nb < 2; nb++) {
                unsigned r0, r1, r2, r3;
                ldsm4(r0, r1, r2, r3,
                      kb + ((wn*32 + nb*16 + b_r)*T_LD + kf*16 + b_c)*2);
                b[nb*2+0][0] = r0; b[nb*2+0][1] = r1;
                b[nb*2+1][0] = r2; b[nb*2+1][1] = r3;
            }
            #pragma unroll
            for (int mf = 0; mf < 2; mf++)
                #pragma unroll
                for (int nf = 0; nf < 4; nf++)
                    mma_f16(s[mf][nf], a[mf], b[nf]);
        }

        #pragma unroll
        for (int mf = 0; mf < 2; mf++) {
            int r0 = wm*32 + mf*16 + quad;
            #pragma unroll
            for (int nf = 0; nf < 4; nf++) {
                int lcol = wn*32 + nf*8 + lane4*2;
                int col  = kt*64 + lcol;
                __stcs((float2*)(raw + (rowg + r0)*SEQ + col),
                       make_float2(s[mf][nf][0], s[mf][nf][1]));
                __stcs((float2*)(raw + (rowg + r0 + 8)*SEQ + col),
                       make_float2(s[mf][nf][2], s[mf][nf][3]));
                float2 m2 = *(const float2*)(mm + col);
                float p00 = m2.x * __expf(s[mf][nf][0]);
                float p01 = m2.y * __expf(s[mf][nf][1]);
                float p10 = m2.x * __expf(s[mf][nf][2]);
                float p11 = m2.y * __expf(s[mf][nf][3]);
                rs[mf][0] += p00 + p01;
                rs[mf][1] += p10 + p11;
                *(__half2*)(Ps + r0*T_LD + lcol)     = __floats2half2_rn(p00, p01);
                *(__half2*)(Ps + (r0+8)*T_LD + lcol) = __floats2half2_rn(p10, p11);
            }
        }

        if (kt < 15) {
            #pragma unroll
            for (int it = 0; it < 4; it++) {
                int t = (kt+1)*64 + lr + it*16;
                rk[it] = *(const uint2*)(ksrc + (size_t)t*HD + ld0);
                rv[it] = *(const uint2*)(vsrc + (size_t)t*HD + ld0);
            }
        }
        __syncthreads();

        #pragma unroll
        for (int tf = 0; tf < 4; tf++) {
            unsigned a[2][4], b[4][2];
            #pragma unroll
            for (int mf = 0; mf < 2; mf++)
                ldsm4(a[mf][0], a[mf][1], a[mf][2], a[mf][3],
                      pb + ((wm*32 + mf*16 + a_r)*T_LD + tf*16 + a_c)*2);
            #pragma unroll
            for (int nb = 0; nb < 2; nb++) {
                unsigned r0, r1, r2, r3;
                ldsm4t(r0, r1, r2, r3,
                       vb + ((tf*16 + (sub & 1)*8 + lr8)*T_LD
                             + wn*32 + nb*16 + (sub >> 1)*8)*2);
                b[nb*2+0][0] = r0; b[nb*2+0][1] = r1;
                b[nb*2+1][0] = r2; b[nb*2+1][1] = r3;
            }
            #pragma unroll
            for (int mf = 0; mf < 2; mf++)
                #pragma unroll
                for (int nf = 0; nf < 4; nf++)
                    mma_f16(o[mf][nf], a[mf], b[nf]);
        }
    }

    #pragma unroll
    for (int mf = 0; mf < 2; mf++)
        #pragma unroll
        for (int rg = 0; rg < 2; rg++) {
            rs[mf][rg] += __shfl_xor_sync(0xffffffffu, rs[mf][rg], 1);
            rs[mf][rg] += __shfl_xor_sync(0xffffffffu, rs[mf][rg], 2);
        }
    if (lane4 == 0) {
        #pragma unroll
        for (int mf = 0; mf < 2; mf++) {
            int r0 = wm*32 + mf*16 + quad;
            ls[wn*128 + r0]     = rs[mf][0];
            ls[wn*128 + r0 + 8] = rs[mf][1];
        }
    }
    __syncthreads();

    #pragma unroll
    for (int mf = 0; mf < 2; mf++) {
        int r0 = wm*32 + mf*16 + quad;
        float inv0 = 1.f / (ls[r0] + ls[128 + r0]);
        float inv1 = 1.f / (ls[r0 + 8] + ls[128 + r0 + 8]);
        __half* adst0 = g_A + (rowg + r0)*HD;
        #pragma unroll
        for (int nf = 0; nf < 4; nf++) {
            int lcol = wn*32 + nf*8 + lane4*2;
            *(__half2*)(adst0 + lcol) =
                __floats2half2_rn(o[mf][nf][0]*inv0, o[mf][nf][1]*inv0);
            *(__half2*)(adst0 + 8*HD + lcol) =
                __floats2half2_rn(o[mf][nf][2]*inv1, o[mf][nf][3]*inv1);
        }
    }
}

// ---------------------------------------------------------------------------
// Output projection, PTX mma, register epilogue, double-buffered smem.
// ---------------------------------------------------------------------------
__global__ __launch_bounds__(256, 2) void proj_out_kernel(
    const float* __restrict__ bo, float* __restrict__ out)
{
    __shared__ __half As[2][128*A_LD];
    __shared__ __half Bs[2][32*B_LD];

    const __half* w = g_wh[3];
    const int m0 = blockIdx.x * 128;
    const int n0 = blockIdx.y * 128;
    const int tid = threadIdx.x;
    const int wid = tid >> 5, lane = tid & 31;
    const int wm = wid >> 1, wn = wid & 1;
    const int quad = lane >> 2, lane4 = lane & 3;
    const int sub = lane >> 3, lr8 = lane & 7;
    const int a_r = (sub & 1)*8 + lr8, a_c = (sub >> 1)*8;

    const int ar = tid >> 3, ac = (tid & 7) * 4;
    const int br = tid >> 5, bc = (tid & 31) * 4;
    const int rowA0 = m0 + ar;

    float o[2][8][4];
    #pragma unroll
    for (int i = 0; i < 2; i++)
        #pragma unroll
        for (int j = 0; j < 8; j++)
            #pragma unroll
            for (int e = 0; e < 4; e++) o[i][j][e] = 0.f;

    float2 bias2[8];
    #pragma unroll
    for (int nf = 0; nf < 8; nf++)
        bias2[nf] = *(const float2*)(bo + n0 + wn*64 + nf*8 + lane4*2);

    uint2 ra[4], rb[4];
    #pragma unroll
    for (int it = 0; it < 4; it++) {
        int row = rowA0 + it*32;
        int b = row >> 10, s = row & 1023;
        ra[it] = *(const uint2*)(g_A + ((size_t)b*SEQ + s)*HD + ac);
    }
    #pragma unroll
    for (int it = 0; it < 4; it++)
        rb[it] = *(const uint2*)(w + (size_t)(br + it*8)*DM + n0 + bc);

    const unsigned ab[2] = {su(As[0]), su(As[1])};
    const unsigned bb[2] = {su(Bs[0]), su(Bs[1])};

    for (int kt = 0; kt < 16; kt++) {
        const int cb = kt & 1;
        #pragma unroll
        for (int it = 0; it < 4; it++)
            *(uint2*)(As[cb] + (ar + it*32)*A_LD + ac) = ra[it];
        #pragma unroll
        for (int it = 0; it < 4; it++)
            *(uint2*)(Bs[cb] + (br + it*8)*B_LD + bc) = rb[it];
        __syncthreads();

        if (kt < 15) {
            int k0 = (kt + 1) * 32;
            int h = k0 >> 6, v0 = k0 & 63;
            #pragma unroll
            for (int it = 0; it < 4; it++) {
                int row = rowA0 + it*32;
                int b = row >> 10, s = row & 1023;
                ra[it] = *(const uint2*)(g_A + (((size_t)(h*BATCH + b))*SEQ + s)*HD + v0 + ac);
            }
            #pragma unroll
            for (int it = 0; it < 4; it++)
                rb[it] = *(const uint2*)(w + (size_t)(k0 + br + it*8)*DM + n0 + bc);
        }

        #pragma unroll
        for (int kf = 0; kf < 2; kf++) {
            unsigned a[2][4], b[8][2];
            #pragma unroll
            for (int mf = 0; mf < 2; mf++)
                ldsm4(a[mf][0], a[mf][1], a[mf][2], a[mf][3],
                      ab[cb] + ((wm*32 + mf*16 + a_r)*A_LD + kf*16 + a_c)*2);
            #pragma unroll
            for (int nb = 0; nb < 4; nb++) {
                unsigned r0, r1, r2, r3;
                ldsm4t(r0, r1, r2, r3,
                       bb[cb] + ((kf*16 + (sub & 1)*8 + lr8)*B_LD
                                 + wn*64 + nb*16 + (sub >> 1)*8)*2);
                b[nb*2+0][0] = r0; b[nb*2+0][1] = r1;
                b[nb*2+1][0] = r2; b[nb*2+1][1] = r3;
            }
            #pragma unroll
            for (int mf = 0; mf < 2; mf++)
                #pragma unroll
                for (int nf = 0; nf < 8; nf++)
                    mma_f16(o[mf][nf], a[mf], b[nf]);
        }
    }

    #pragma unroll
    for (int mf = 0; mf < 2; mf++) {
        int row0 = m0 + wm*32 + mf*16 + quad;
        #pragma unroll
        for (int nf = 0; nf < 8; nf++) {
            int col = n0 + wn*64 + nf*8 + lane4*2;
            __stcs((float2*)(out + (size_t)row0*DM + col),
                   make_float2(o[mf][nf][0] + bias2[nf].x,
                               o[mf][nf][1] + bias2[nf].y));
            __stcs((float2*)(out + (size_t)(row0+8)*DM + col),
                   make_float2(o[mf][nf][2] + bias2[nf].x,
                               o[mf][nf][3] + bias2[nf].y));
        }
    }
}

// ---------------------------------------------------------------------------
extern "C" void kernel_launch(void* const* d_in, const int* in_sizes, int n_in,
                              void* d_out, int out_size)
{
    (void)in_sizes; (void)n_in; (void)out_size;
    const float* x  = (const float*)d_in[0];
    const int*   pm = (const int*)  d_in[1];
    const float* wq = (const float*)d_in[2];
    const float* bq = (const float*)d_in[3];
    const float* wk = (const float*)d_in[4];
    const float* bk = (const float*)d_in[5];
    const float* wv = (const float*)d_in[6];
    const float* bv = (const float*)d_in[7];
    const float* wo = (const float*)d_in[8];
    const float* bo = (const float*)d_in[9];

    float* out = (float*)d_out;
    float* raw = out + (size_t)BATCH*SEQ*DM;

    cudaFuncSetAttribute(attn_kernel, cudaFuncAttributeMaxDynamicSharedMemorySize,
                         ATTN_SMEM);

    __half* xh;
    cudaGetSymbolAddress((void**)&xh, g_xh);

    const int NX = BATCH*SEQ*DM, NW = DM*DM;
    cvt_kernel<<<NX/1024, 256>>>(x, xh, NX);
    cvt_w_kernel<<<dim3(NW/1024, 4), 256>>>(wq, wk, wv, wo);

    proj_qkv_kernel<<<dim3(BATCH*SEQ/128, DM/128, 3), 256>>>(bq, bk, bv);
    attn_kernel<<<dim3(SEQ/QT_ROWS, NB), 256, ATTN_SMEM>>>(pm, raw);
    proj_out_kernel<<<dim3(BATCH*SEQ/128, DM/128), 256>>>(bo, out);
}